// round 6
// baseline (speedup 1.0000x reference)
#include <cuda_runtime.h>
#include <math.h>

// Problem constants (fixed shapes from reference setup_inputs)
#define NN 16
#define CC 256
#define HH 64
#define WW 64
#define HW (HH * WW)        // 4096
#define K2 9
#define BN_EPS 1e-5f

// Scratch (device globals; no allocation allowed)
__device__ float g_h[NN * CC * HW];      // conv1 output after BN+PReLU  (~67 MB)
__device__ float g_kern[NN * K2 * HW];   // dynamic per-pixel kernel [N,9,H*W]

// ---------------------------------------------------------------------------
// Kernel 1: 3x3 conv (C->C, pad=1) + BN + PReLU
// Tiling: block = 128 threads = 8 rows x 16 col-groups (4 px each) -> 8x64 tile
//         each thread accumulates 16 output channels x 4 pixels.
// Grid: (C/16 co-groups, H/8 row-tiles, N)
// ---------------------------------------------------------------------------
#define CI_CHUNK 4
#define CO_BLK   16

__global__ __launch_bounds__(128, 4)
void conv3x3_bn_prelu(const float* __restrict__ y,
                      const float* __restrict__ W1,
                      const float* __restrict__ g1,
                      const float* __restrict__ b1,
                      const float* __restrict__ m1,
                      const float* __restrict__ v1,
                      const float* __restrict__ a1)
{
    __shared__ float sy[CI_CHUNK][10][66];          // input tile, +1 halo each side
    __shared__ float sw[CI_CHUNK][CO_BLK][9];       // weights

    const int tx   = threadIdx.x;
    const int trow = tx >> 4;          // 0..7
    const int tw   = tx & 15;          // 0..15, covers cols [4*tw, 4*tw+3]
    const int cob  = blockIdx.x * CO_BLK;
    const int h0   = blockIdx.y * 8;
    const int n    = blockIdx.z;

    float acc[CO_BLK][4];
#pragma unroll
    for (int co = 0; co < CO_BLK; co++)
#pragma unroll
        for (int p = 0; p < 4; p++) acc[co][p] = 0.f;

    const float* yn = y + (size_t)n * CC * HW;

    for (int ci0 = 0; ci0 < CC; ci0 += CI_CHUNK) {
        __syncthreads();
        // cooperative load of y tile: CI_CHUNK x 10 rows x 66 cols (zero pad)
        for (int i = tx; i < CI_CHUNK * 10 * 66; i += 128) {
            int ci  = i / 660;
            int rem = i - ci * 660;
            int r   = rem / 66;
            int c   = rem - r * 66;
            int gr  = h0 - 1 + r;
            int gc  = c - 1;
            float val = 0.f;
            if (gr >= 0 && gr < HH && gc >= 0 && gc < WW)
                val = yn[(ci0 + ci) * HW + gr * WW + gc];
            sy[ci][r][c] = val;
        }
        // cooperative load of weights: CI_CHUNK x CO_BLK x 9
        for (int i = tx; i < CI_CHUNK * CO_BLK * 9; i += 128) {
            int ci  = i / (CO_BLK * 9);
            int rem = i - ci * (CO_BLK * 9);
            int co  = rem / 9;
            int k   = rem - co * 9;
            sw[ci][co][k] = W1[((size_t)(cob + co) * CC + (ci0 + ci)) * 9 + k];
        }
        __syncthreads();

#pragma unroll
        for (int ci = 0; ci < CI_CHUNK; ci++) {
            // load 3x6 taps for this thread's 4 output pixels
            float t[3][6];
#pragma unroll
            for (int r = 0; r < 3; r++)
#pragma unroll
                for (int c = 0; c < 6; c++)
                    t[r][c] = sy[ci][trow + r][4 * tw + c];

#pragma unroll
            for (int co = 0; co < CO_BLK; co++) {
#pragma unroll
                for (int kh = 0; kh < 3; kh++) {
#pragma unroll
                    for (int kw = 0; kw < 3; kw++) {
                        float w = sw[ci][co][kh * 3 + kw];
#pragma unroll
                        for (int p = 0; p < 4; p++)
                            acc[co][p] = fmaf(w, t[kh][p + kw], acc[co][p]);
                    }
                }
            }
        }
    }

    // epilogue: BN (eval) + PReLU, write to g_h
    const float alpha = a1[0];
    const int   orow  = h0 + trow;
    const int   ocol  = 4 * tw;
#pragma unroll
    for (int co = 0; co < CO_BLK; co++) {
        int ch = cob + co;
        float sc = g1[ch] * rsqrtf(v1[ch] + BN_EPS);
        float sh = b1[ch] - m1[ch] * sc;
        float* dst = g_h + ((size_t)n * CC + ch) * HW + orow * WW + ocol;
#pragma unroll
        for (int p = 0; p < 4; p++) {
            float v = acc[co][p] * sc + sh;
            dst[p] = (v >= 0.f) ? v : alpha * v;
        }
    }
}

// ---------------------------------------------------------------------------
// Kernel 2: 1x1 conv (C->9) + BN + PReLU -> g_kern [N,9,H*W]
// one thread per pixel, loop over 256 input channels
// ---------------------------------------------------------------------------
__global__ __launch_bounds__(256)
void conv1x1_bn_prelu(const float* __restrict__ W2,
                      const float* __restrict__ g2,
                      const float* __restrict__ b2,
                      const float* __restrict__ m2,
                      const float* __restrict__ v2,
                      const float* __restrict__ a2)
{
    __shared__ float w2s[K2][CC];
    const int tx = threadIdx.x;
    for (int i = tx; i < K2 * CC; i += 256) {
        int k  = i / CC;
        int ci = i - k * CC;
        w2s[k][ci] = W2[k * CC + ci];
    }
    __syncthreads();

    int pix = blockIdx.x * 256 + tx;          // 0 .. N*HW-1
    int n   = pix / HW;
    int hw  = pix - n * HW;

    float acc[K2];
#pragma unroll
    for (int k = 0; k < K2; k++) acc[k] = 0.f;

    const float* hp = g_h + (size_t)n * CC * HW + hw;
    for (int ci = 0; ci < CC; ci++) {
        float v = hp[(size_t)ci * HW];
#pragma unroll
        for (int k = 0; k < K2; k++)
            acc[k] = fmaf(v, w2s[k][ci], acc[k]);
    }

    const float alpha = a2[0];
#pragma unroll
    for (int k = 0; k < K2; k++) {
        float sc = g2[k] * rsqrtf(v2[k] + BN_EPS);
        float sh = b2[k] - m2[k] * sc;
        float v  = acc[k] * sc + sh;
        v = (v >= 0.f) ? v : alpha * v;
        g_kern[((size_t)n * K2 + k) * HW + hw] = v;
    }
}

// ---------------------------------------------------------------------------
// Kernel 3: apply dynamic per-pixel kernel, reproducing torch's ROW-MAJOR
// reshape of unfold output [N, C*9, H*W] into [N, H, W, C, 9].
//
// out[n,c,P] = sum_{k=0..8} A[n, P*2304 + c*9 + k] * kern[n, P, k]
// where A is the virtual unfold buffer in [C,9,H,W] order:
//   A[n, f]: c2=f/36864, k2=(f/4096)%9, h2=(f/64)%64, w2=f%64
//   A[n, f] = x_pad[n, c2, h2 + k2/3 - 1, w2 + k2%3 - 1]
//
// Block: G=4 consecutive P slabs staged in smem (slab = 2304 floats, padded
// to 2305 to avoid bank alignment), 256 threads. Thread c computes the 4
// outputs out[n, c, P0..P0+3] (consecutive in memory).
// ---------------------------------------------------------------------------
#define G_P 4
#define SLAB 2304
#define SLABP 2305

__global__ __launch_bounds__(256)
void apply_dynamic_kernel(const float* __restrict__ x,
                          float* __restrict__ out)
{
    __shared__ float sA[G_P * SLABP];
    __shared__ float sk[G_P][K2];

    const int tid = threadIdx.x;
    const int P0  = blockIdx.x * G_P;
    const int n   = blockIdx.y;

    // load the G_P per-pixel kernels (9 taps each)
    if (tid < G_P * K2) {
        int p = tid / K2;
        int k = tid - p * K2;
        sk[p][k] = g_kern[((size_t)n * K2 + k) * HW + P0 + p];
    }

    const float* xn = x + (size_t)n * CC * HW;
    const int base = P0 * SLAB;

    // stage G_P contiguous slabs of the virtual unfold buffer
    for (int t = tid; t < G_P * SLAB; t += 256) {
        int flat = base + t;
        int w2 = flat & 63;
        int j  = flat >> 6;          // global row index
        int h2 = j & 63;
        int q  = j >> 6;             // c2*9 + k2
        int k2 = q % 9;
        int c2 = q / 9;
        int r  = k2 / 3;
        int s  = k2 - r * 3;
        int ih = h2 + r - 1;
        int iw = w2 + s - 1;
        float v = 0.f;
        if (ih >= 0 && ih < HH && iw >= 0 && iw < WW)
            v = xn[c2 * HW + ih * WW + iw];
        int slab = t / SLAB;
        int off  = t - slab * SLAB;
        sA[slab * SLABP + off] = v;
    }
    __syncthreads();

    // thread c computes out[n, c, P0 + p] for p = 0..G_P-1
    const int c = tid;
    float res[G_P];
#pragma unroll
    for (int p = 0; p < G_P; p++) {
        const float* a = sA + p * SLABP + c * K2;
        float acc = 0.f;
#pragma unroll
        for (int k = 0; k < K2; k++)
            acc = fmaf(a[k], sk[p][k], acc);
        res[p] = acc;
    }

    float* dst = out + ((size_t)n * CC + c) * HW + P0;
#pragma unroll
    for (int p = 0; p < G_P; p++) dst[p] = res[p];
}

// ---------------------------------------------------------------------------
extern "C" void kernel_launch(void* const* d_in, const int* in_sizes, int n_in,
                              void* d_out, int out_size)
{
    const float* x  = (const float*)d_in[0];
    const float* y  = (const float*)d_in[1];
    const float* W1 = (const float*)d_in[2];
    const float* g1 = (const float*)d_in[3];
    const float* b1 = (const float*)d_in[4];
    const float* m1 = (const float*)d_in[5];
    const float* v1 = (const float*)d_in[6];
    const float* a1 = (const float*)d_in[7];
    const float* W2 = (const float*)d_in[8];
    const float* g2 = (const float*)d_in[9];
    const float* b2 = (const float*)d_in[10];
    const float* m2 = (const float*)d_in[11];
    const float* v2 = (const float*)d_in[12];
    const float* a2 = (const float*)d_in[13];
    float* out = (float*)d_out;

    // Kernel 1: 3x3 conv + BN + PReLU
    {
        dim3 grid(CC / CO_BLK, HH / 8, NN);   // (16, 8, 16)
        conv3x3_bn_prelu<<<grid, 128>>>(y, W1, g1, b1, m1, v1, a1);
    }
    // Kernel 2: 1x1 conv + BN + PReLU
    {
        int blocks = (NN * HW) / 256;         // 256 blocks
        conv1x1_bn_prelu<<<blocks, 256>>>(W2, g2, b2, m2, v2, a2);
    }
    // Kernel 3: dynamic filter application (scrambled-reshape semantics)
    {
        dim3 grid(HW / G_P, NN);              // (1024, 16)
        apply_dynamic_kernel<<<grid, 256>>>(x, out);
    }
}

// round 8
// speedup vs baseline: 2.2139x; 2.2139x over previous
#include <cuda_runtime.h>
#include <cuda_bf16.h>
#include <math.h>
#include <stdint.h>

// Problem constants
#define NN 16
#define CC 256
#define HH 64
#define WW 64
#define HW (HH * WW)        // 4096
#define K2 9
#define BN_EPS 1e-5f

// Scratch (device globals; no allocation allowed)
__device__ float g_h[NN * CC * HW];                         // conv1 out (BN+PReLU)
__device__ float g_kern[NN * K2 * HW];                      // dyn kernel [N,9,H*W]
__device__ __align__(16) __nv_bfloat16 g_wth[K2 * CC * CC]; // W1 hi [tap][co][ci]
__device__ __align__(16) __nv_bfloat16 g_wtl[K2 * CC * CC]; // W1 lo
__device__ __align__(16) __nv_bfloat16 g_yth[NN * HW * CC]; // y hi K-major [n][pix][ci]
__device__ __align__(16) __nv_bfloat16 g_ytl[NN * HW * CC]; // y lo

// ===========================================================================
// mma.sync / ldmatrix helpers (baseline PTX, valid at compute_103)
// ===========================================================================
__device__ __forceinline__ uint32_t smem_u32(const void* p) {
    uint32_t a;
    asm("{ .reg .u64 t; cvta.to.shared.u64 t, %1; cvt.u32.u64 %0, t; }"
        : "=r"(a) : "l"(p));
    return a;
}
__device__ __forceinline__ void ldsm4(uint32_t& r0, uint32_t& r1,
                                      uint32_t& r2, uint32_t& r3, uint32_t addr) {
    asm volatile("ldmatrix.sync.aligned.m8n8.x4.shared.b16 {%0,%1,%2,%3}, [%4];"
                 : "=r"(r0), "=r"(r1), "=r"(r2), "=r"(r3) : "r"(addr));
}
__device__ __forceinline__ void mma_bf16(float* c, const uint32_t* a, const uint32_t* b) {
    asm volatile("mma.sync.aligned.m16n8k16.row.col.f32.bf16.bf16.f32 "
                 "{%0,%1,%2,%3}, {%4,%5,%6,%7}, {%8,%9}, {%0,%1,%2,%3};"
                 : "+f"(c[0]), "+f"(c[1]), "+f"(c[2]), "+f"(c[3])
                 : "r"(a[0]), "r"(a[1]), "r"(a[2]), "r"(a[3]), "r"(b[0]), "r"(b[1]));
}

// ===========================================================================
// Prep A: W1 [co][ci][3][3] fp32 -> wt hi/lo [tap][co][ci] bf16
// ===========================================================================
__global__ __launch_bounds__(256)
void prep_weights(const float* __restrict__ W1)
{
    int idx = blockIdx.x * 256 + threadIdx.x;     // over 9*256*256
    if (idx >= K2 * CC * CC) return;
    int k   = idx >> 16;
    int rem = idx & 0xFFFF;
    int co  = rem >> 8;
    int ci  = rem & 255;
    float v = W1[((size_t)co * CC + ci) * 9 + k];
    __nv_bfloat16 h = __float2bfloat16(v);
    __nv_bfloat16 l = __float2bfloat16(v - __bfloat162float(h));
    g_wth[idx] = h;
    g_wtl[idx] = l;
}

// ===========================================================================
// Prep B: transpose y [n][ci][p] fp32 -> yt hi/lo [n][p][ci] bf16
// ===========================================================================
__global__ __launch_bounds__(256)
void prep_y_transpose(const float* __restrict__ y)
{
    __shared__ float s[32][33];
    const int n  = blockIdx.z;
    const int p0 = blockIdx.x * 32;
    const int c0 = blockIdx.y * 32;
    const int tx = threadIdx.x;
    const int j  = tx & 31;
    const int i  = tx >> 5;            // 0..7

#pragma unroll
    for (int it = 0; it < 4; it++) {
        int ci = c0 + i + it * 8;
        s[i + it * 8][j] = y[((size_t)n * CC + ci) * HW + p0 + j];
    }
    __syncthreads();
#pragma unroll
    for (int it = 0; it < 4; it++) {
        int pl = i + it * 8;
        float v = s[j][pl];
        __nv_bfloat16 h = __float2bfloat16(v);
        __nv_bfloat16 l = __float2bfloat16(v - __bfloat162float(h));
        size_t o = ((size_t)n * HW + p0 + pl) * CC + c0 + j;
        g_yth[o] = h;
        g_ytl[o] = l;
    }
}

// ===========================================================================
// Kernel 1: conv3x3 as 9-tap GEMM on mma.sync (bf16 hi/lo split, fp32 acc)
// CTA tile: M=128 co x N=256 pix. 8 warps (2 m x 4 n), warp tile 64x64.
// K loop: 9 taps x 4 ci-chunks of 64 -> 36 stage+compute iterations.
// Smem rows padded to 72 halves (144B): ldmatrix rows land on distinct banks.
// ===========================================================================
#define LDH 72                          // halves per padded row
#define LDB 144                         // bytes per padded row
#define OFF_AH 0
#define OFF_AL (128 * LDB)              // 18432
#define OFF_BH (2 * 128 * LDB)          // 36864
#define OFF_BL (OFF_BH + 256 * LDB)     // 73728
#define CONV_SMEM (OFF_BL + 256 * LDB)  // 110592

__global__ __launch_bounds__(256, 1)
void conv3x3_mma(const float* __restrict__ g1,
                 const float* __restrict__ b1,
                 const float* __restrict__ m1,
                 const float* __restrict__ v1,
                 const float* __restrict__ a1)
{
    extern __shared__ char sb[];
    const uint32_t sb32 = smem_u32(sb);

    const int tid  = threadIdx.x;
    const int wid  = tid >> 5;
    const int lane = tid & 31;
    const int wm   = wid >> 2;          // 0..1  (co 64-block)
    const int wn   = wid & 3;           // 0..3  (pix 64-block)
    const int P0   = blockIdx.x * 256;
    const int cob  = blockIdx.y * 128;
    const int n    = blockIdx.z;

    const int quad = lane >> 3;         // 0..3
    const int lrow = lane & 7;

    // ldmatrix lane-address components (see fragment mapping in PTX ISA)
    // A (row-major 16x16): quad0: r+0 k+0 | quad1: r+8 k+0 | quad2: r+0 k+8 | quad3: r+8 k+8
    const int armBase = wm * 64 + lrow + ((quad & 1) << 3);
    const int akAdd   = (quad >> 1) << 3;
    // B pair of n8 tiles (col 16x16): quad0: n+0 k+0 | quad1: n+0 k+8 | quad2: n+8 k+0 | quad3: n+8 k+8
    const int bnBase = wn * 64 + lrow + ((quad >> 1) << 3);
    const int bkAdd  = (quad & 1) << 3;

    float acc[4][8][4];
#pragma unroll
    for (int mt = 0; mt < 4; mt++)
#pragma unroll
        for (int nt = 0; nt < 8; nt++)
#pragma unroll
            for (int i = 0; i < 4; i++) acc[mt][nt][i] = 0.f;

    for (int tap = 0; tap < 9; tap++) {
        const int dr = tap / 3 - 1;
        const int ds = tap - (tap / 3) * 3 - 1;

        for (int ci0 = 0; ci0 < CC; ci0 += 64) {
            __syncthreads();
            // ---- stage A hi/lo: 128 rows x 64 halves (8 uint4/row)
            for (int i = tid; i < 1024; i += 256) {
                int r = i >> 3, q = i & 7;
                size_t src = ((size_t)tap << 16) + ((size_t)(cob + r) << 8) + ci0;
                uint4 vh = ((const uint4*)(g_wth + src))[q];
                uint4 vl = ((const uint4*)(g_wtl + src))[q];
                *(uint4*)(sb + OFF_AH + r * LDB + q * 16) = vh;
                *(uint4*)(sb + OFF_AL + r * LDB + q * 16) = vl;
            }
            // ---- stage B hi/lo: 256 rows (pixels) x 64 halves, tap-shifted
            for (int i = tid; i < 2048; i += 256) {
                int r = i >> 3, q = i & 7;
                int p  = P0 + r;
                int hs = (p >> 6) + dr;
                int ws = (p & 63) + ds;
                bool valid = ((unsigned)hs < HH) && ((unsigned)ws < WW);
                uint4 vh = make_uint4(0, 0, 0, 0), vl = vh;
                if (valid) {
                    size_t src = ((size_t)n * HW + hs * WW + ws) * CC + ci0;
                    vh = ((const uint4*)(g_yth + src))[q];
                    vl = ((const uint4*)(g_ytl + src))[q];
                }
                *(uint4*)(sb + OFF_BH + r * LDB + q * 16) = vh;
                *(uint4*)(sb + OFF_BL + r * LDB + q * 16) = vl;
            }
            __syncthreads();

            // ---- compute: 4 k-steps of 16
#pragma unroll
            for (int kk = 0; kk < 4; kk++) {
                const int k0 = kk * 16;
                uint32_t ah[4][4], al[4][4], bh[8][2], bl[8][2];
#pragma unroll
                for (int mt = 0; mt < 4; mt++) {
                    uint32_t aoff = (uint32_t)((armBase + mt * 16) * LDB +
                                               (k0 + akAdd) * 2);
                    ldsm4(ah[mt][0], ah[mt][1], ah[mt][2], ah[mt][3],
                          sb32 + OFF_AH + aoff);
                    ldsm4(al[mt][0], al[mt][1], al[mt][2], al[mt][3],
                          sb32 + OFF_AL + aoff);
                }
#pragma unroll
                for (int ntp = 0; ntp < 4; ntp++) {
                    uint32_t boff = (uint32_t)((bnBase + ntp * 16) * LDB +
                                               (k0 + bkAdd) * 2);
                    ldsm4(bh[2 * ntp][0], bh[2 * ntp][1],
                          bh[2 * ntp + 1][0], bh[2 * ntp + 1][1],
                          sb32 + OFF_BH + boff);
                    ldsm4(bl[2 * ntp][0], bl[2 * ntp][1],
                          bl[2 * ntp + 1][0], bl[2 * ntp + 1][1],
                          sb32 + OFF_BL + boff);
                }
#pragma unroll
                for (int mt = 0; mt < 4; mt++) {
#pragma unroll
                    for (int nt = 0; nt < 8; nt++) {
                        mma_bf16(acc[mt][nt], ah[mt], bh[nt]);   // hi*hi
                        mma_bf16(acc[mt][nt], ah[mt], bl[nt]);   // hi*lo
                        mma_bf16(acc[mt][nt], al[mt], bh[nt]);   // lo*hi
                    }
                }
            }
        }
    }

    // ---- epilogue: BN + PReLU, store float2 pairs
    const float alpha = a1[0];
#pragma unroll
    for (int mt = 0; mt < 4; mt++) {
        int r0  = wm * 64 + mt * 16 + (lane >> 2);
        int co0 = cob + r0;
        int co1 = co0 + 8;
        float sc0 = g1[co0] * rsqrtf(v1[co0] + BN_EPS);
        float sh0 = b1[co0] - m1[co0] * sc0;
        float sc1 = g1[co1] * rsqrtf(v1[co1] + BN_EPS);
        float sh1 = b1[co1] - m1[co1] * sc1;
        float* base0 = g_h + ((size_t)n * CC + co0) * HW;
        float* base1 = g_h + ((size_t)n * CC + co1) * HW;
#pragma unroll
        for (int nt = 0; nt < 8; nt++) {
            int col = P0 + wn * 64 + nt * 8 + 2 * (lane & 3);
            float v0 = acc[mt][nt][0] * sc0 + sh0;
            float v1_ = acc[mt][nt][1] * sc0 + sh0;
            float v2 = acc[mt][nt][2] * sc1 + sh1;
            float v3 = acc[mt][nt][3] * sc1 + sh1;
            float2 o0, o1;
            o0.x = (v0 >= 0.f) ? v0 : alpha * v0;
            o0.y = (v1_ >= 0.f) ? v1_ : alpha * v1_;
            o1.x = (v2 >= 0.f) ? v2 : alpha * v2;
            o1.y = (v3 >= 0.f) ? v3 : alpha * v3;
            *(float2*)(base0 + col) = o0;
            *(float2*)(base1 + col) = o1;
        }
    }
}

// ===========================================================================
// Kernel 2: 1x1 conv (C->9) + BN + PReLU -> g_kern [N,9,H*W]
// ===========================================================================
__global__ __launch_bounds__(256)
void conv1x1_bn_prelu(const float* __restrict__ W2,
                      const float* __restrict__ g2,
                      const float* __restrict__ b2,
                      const float* __restrict__ m2,
                      const float* __restrict__ v2,
                      const float* __restrict__ a2)
{
    __shared__ float w2s[K2][CC];
    const int tx = threadIdx.x;
    for (int i = tx; i < K2 * CC; i += 256) {
        int k  = i / CC;
        int ci = i - k * CC;
        w2s[k][ci] = W2[k * CC + ci];
    }
    __syncthreads();

    int pix = blockIdx.x * 256 + tx;
    int n   = pix / HW;
    int hw  = pix - n * HW;

    float acc[K2];
#pragma unroll
    for (int k = 0; k < K2; k++) acc[k] = 0.f;

    const float* hp = g_h + (size_t)n * CC * HW + hw;
    for (int ci = 0; ci < CC; ci++) {
        float v = hp[(size_t)ci * HW];
#pragma unroll
        for (int k = 0; k < K2; k++)
            acc[k] = fmaf(v, w2s[k][ci], acc[k]);
    }

    const float alpha = a2[0];
#pragma unroll
    for (int k = 0; k < K2; k++) {
        float sc = g2[k] * rsqrtf(v2[k] + BN_EPS);
        float sh = b2[k] - m2[k] * sc;
        float v  = acc[k] * sc + sh;
        v = (v >= 0.f) ? v : alpha * v;
        g_kern[((size_t)n * K2 + k) * HW + hw] = v;
    }
}

// ===========================================================================
// Kernel 3: dynamic filter application with torch's ROW-MAJOR reshape scramble
// ===========================================================================
#define G_P 4
#define SLAB 2304
#define SLABP 2305

__global__ __launch_bounds__(256)
void apply_dynamic_kernel(const float* __restrict__ x,
                          float* __restrict__ out)
{
    __shared__ float sA[G_P * SLABP];
    __shared__ float sk[G_P][K2];

    const int tid = threadIdx.x;
    const int P0  = blockIdx.x * G_P;
    const int n   = blockIdx.y;

    if (tid < G_P * K2) {
        int p = tid / K2;
        int k = tid - p * K2;
        sk[p][k] = g_kern[((size_t)n * K2 + k) * HW + P0 + p];
    }

    const float* xn = x + (size_t)n * CC * HW;
    const int base = P0 * SLAB;

    for (int t = tid; t < G_P * SLAB; t += 256) {
        int flat = base + t;
        int w2 = flat & 63;
        int j  = flat >> 6;
        int h2 = j & 63;
        int q  = j >> 6;             // c2*9 + k2
        int k2 = q % 9;
        int c2 = q / 9;
        int r  = k2 / 3;
        int s  = k2 - r * 3;
        int ih = h2 + r - 1;
        int iw = w2 + s - 1;
        float v = 0.f;
        if (ih >= 0 && ih < HH && iw >= 0 && iw < WW)
            v = xn[c2 * HW + ih * WW + iw];
        int slab = t / SLAB;
        int off  = t - slab * SLAB;
        sA[slab * SLABP + off] = v;
    }
    __syncthreads();

    const int c = tid;
    float res[G_P];
#pragma unroll
    for (int p = 0; p < G_P; p++) {
        const float* a = sA + p * SLABP + c * K2;
        float acc = 0.f;
#pragma unroll
        for (int k = 0; k < K2; k++)
            acc = fmaf(a[k], sk[p][k], acc);
        res[p] = acc;
    }

    float* dst = out + ((size_t)n * CC + c) * HW + P0;
#pragma unroll
    for (int p = 0; p < G_P; p++) dst[p] = res[p];
}

// ===========================================================================
extern "C" void kernel_launch(void* const* d_in, const int* in_sizes, int n_in,
                              void* d_out, int out_size)
{
    const float* x  = (const float*)d_in[0];
    const float* y  = (const float*)d_in[1];
    const float* W1 = (const float*)d_in[2];
    const float* g1 = (const float*)d_in[3];
    const float* b1 = (const float*)d_in[4];
    const float* m1 = (const float*)d_in[5];
    const float* v1 = (const float*)d_in[6];
    const float* a1 = (const float*)d_in[7];
    const float* W2 = (const float*)d_in[8];
    const float* g2 = (const float*)d_in[9];
    const float* b2 = (const float*)d_in[10];
    const float* m2 = (const float*)d_in[11];
    const float* v2 = (const float*)d_in[12];
    const float* a2 = (const float*)d_in[13];
    float* out = (float*)d_out;

    static bool attr_set = false;
    if (!attr_set) {
        cudaFuncSetAttribute(conv3x3_mma,
                             cudaFuncAttributeMaxDynamicSharedMemorySize,
                             CONV_SMEM);
        attr_set = true;
    }

    // prep: weight reshape + y transpose to bf16 hi/lo
    prep_weights<<<(K2 * CC * CC + 255) / 256, 256>>>(W1);
    {
        dim3 g(HW / 32, CC / 32, NN);    // (128, 8, 16)
        prep_y_transpose<<<g, 256>>>(y);
    }
    // conv1 on mma.sync tensor cores
    {
        dim3 g(HW / 256, CC / 128, NN);  // (16, 2, 16) = 512 CTAs
        conv3x3_mma<<<g, 256, CONV_SMEM>>>(g1, b1, m1, v1, a1);
    }
    // 1x1 conv
    conv1x1_bn_prelu<<<(NN * HW) / 256, 256>>>(W2, g2, b2, m2, v2, a2);
    // dynamic filter application
    {
        dim3 g(HW / G_P, NN);            // (1024, 16)
        apply_dynamic_kernel<<<g, 256>>>(x, out);
    }
}

// round 9
// speedup vs baseline: 2.7986x; 1.2641x over previous
#include <cuda_runtime.h>
#include <cuda_bf16.h>
#include <math.h>
#include <stdint.h>

// Problem constants
#define NN 16
#define CC 256
#define HH 64
#define WW 64
#define HW (HH * WW)        // 4096
#define K2 9
#define BN_EPS 1e-5f

// Scratch (device globals; no allocation allowed)
__device__ float g_h[NN * CC * HW];                         // conv1 out (BN+PReLU)
__device__ float g_kern[NN * K2 * HW];                      // dyn kernel [N,9,H*W]
__device__ __align__(16) __nv_bfloat16 g_wth[K2 * CC * CC]; // W1 hi [tap][co][ci]
__device__ __align__(16) __nv_bfloat16 g_wtl[K2 * CC * CC]; // W1 lo
__device__ __align__(16) __nv_bfloat16 g_yth[NN * HW * CC]; // y hi K-major [n][pix][ci]
__device__ __align__(16) __nv_bfloat16 g_ytl[NN * HW * CC]; // y lo

// ===========================================================================
// mma.sync / ldmatrix / cp.async helpers (baseline PTX, valid at compute_103)
// ===========================================================================
__device__ __forceinline__ uint32_t smem_u32(const void* p) {
    uint32_t a;
    asm("{ .reg .u64 t; cvta.to.shared.u64 t, %1; cvt.u32.u64 %0, t; }"
        : "=r"(a) : "l"(p));
    return a;
}
__device__ __forceinline__ void ldsm4(uint32_t& r0, uint32_t& r1,
                                      uint32_t& r2, uint32_t& r3, uint32_t addr) {
    asm volatile("ldmatrix.sync.aligned.m8n8.x4.shared.b16 {%0,%1,%2,%3}, [%4];"
                 : "=r"(r0), "=r"(r1), "=r"(r2), "=r"(r3) : "r"(addr));
}
__device__ __forceinline__ void mma_bf16(float* c, const uint32_t* a, const uint32_t* b) {
    asm volatile("mma.sync.aligned.m16n8k16.row.col.f32.bf16.bf16.f32 "
                 "{%0,%1,%2,%3}, {%4,%5,%6,%7}, {%8,%9}, {%0,%1,%2,%3};"
                 : "+f"(c[0]), "+f"(c[1]), "+f"(c[2]), "+f"(c[3])
                 : "r"(a[0]), "r"(a[1]), "r"(a[2]), "r"(a[3]), "r"(b[0]), "r"(b[1]));
}
__device__ __forceinline__ void cp16(uint32_t dst, const void* src, int srcsz) {
    asm volatile("cp.async.cg.shared.global [%0], [%1], 16, %2;"
                 :: "r"(dst), "l"(src), "r"(srcsz) : "memory");
}
#define CP_COMMIT() asm volatile("cp.async.commit_group;" ::: "memory")
#define CP_WAIT1()  asm volatile("cp.async.wait_group 1;" ::: "memory")
#define CP_WAIT0()  asm volatile("cp.async.wait_group 0;" ::: "memory")

// ===========================================================================
// Prep A: W1 [co][ci][3][3] fp32 -> wt hi/lo [tap][co][ci] bf16
// ===========================================================================
__global__ __launch_bounds__(256)
void prep_weights(const float* __restrict__ W1)
{
    int idx = blockIdx.x * 256 + threadIdx.x;     // over 9*256*256
    if (idx >= K2 * CC * CC) return;
    int k   = idx >> 16;
    int rem = idx & 0xFFFF;
    int co  = rem >> 8;
    int ci  = rem & 255;
    float v = W1[((size_t)co * CC + ci) * 9 + k];
    __nv_bfloat16 h = __float2bfloat16(v);
    __nv_bfloat16 l = __float2bfloat16(v - __bfloat162float(h));
    g_wth[idx] = h;
    g_wtl[idx] = l;
}

// ===========================================================================
// Prep B: transpose y [n][ci][p] fp32 -> yt hi/lo [n][p][ci] bf16
// ===========================================================================
__global__ __launch_bounds__(256)
void prep_y_transpose(const float* __restrict__ y)
{
    __shared__ float s[32][33];
    const int n  = blockIdx.z;
    const int p0 = blockIdx.x * 32;
    const int c0 = blockIdx.y * 32;
    const int tx = threadIdx.x;
    const int j  = tx & 31;
    const int i  = tx >> 5;            // 0..7

#pragma unroll
    for (int it = 0; it < 4; it++) {
        int ci = c0 + i + it * 8;
        s[i + it * 8][j] = y[((size_t)n * CC + ci) * HW + p0 + j];
    }
    __syncthreads();
#pragma unroll
    for (int it = 0; it < 4; it++) {
        int pl = i + it * 8;
        float v = s[j][pl];
        __nv_bfloat16 h = __float2bfloat16(v);
        __nv_bfloat16 l = __float2bfloat16(v - __bfloat162float(h));
        size_t o = ((size_t)n * HW + p0 + pl) * CC + c0 + j;
        g_yth[o] = h;
        g_ytl[o] = l;
    }
}

// ===========================================================================
// Kernel 1: conv3x3 as 9-tap GEMM on mma.sync, bf16 hi/lo split, fp32 acc.
// CTA tile: M=128 co x N=256 pix (4 image rows). 8 warps, warp tile 64x64.
// NEW: ci-chunk outer / tap inner. B staged ONCE per chunk as an extended
// 6x66-pixel halo region (396 rows, zeros at image border); all 9 taps read
// it via per-lane computed ldmatrix row addresses. A double-buffered across
// taps with cp.async commit-group pipelining.
// Rows padded to 144B -> conflict-free, 16B-aligned ldmatrix.
// ===========================================================================
#define LDB 144                         // bytes per padded smem row
#define A_HL  (128 * LDB)               // lo offset inside an A buffer (18432)
#define A_BUF (2 * 128 * LDB)           // one A buffer hi+lo (36864)
#define OFF_A 0
#define OFF_BH (2 * A_BUF)              // 73728
#define EXTR 396                        // 6*66 extended pixel rows
#define OFF_BL (OFF_BH + EXTR * LDB)    // 130752
#define CONV_SMEM (OFF_BL + EXTR * LDB) // 187776

__global__ __launch_bounds__(256, 1)
void conv3x3_mma(const float* __restrict__ g1,
                 const float* __restrict__ b1,
                 const float* __restrict__ m1,
                 const float* __restrict__ v1,
                 const float* __restrict__ a1)
{
    extern __shared__ char sb[];
    const uint32_t sb32 = smem_u32(sb);

    const int tid  = threadIdx.x;
    const int wid  = tid >> 5;
    const int lane = tid & 31;
    const int wm   = wid >> 2;          // 0..1  (co 64-block)
    const int wn   = wid & 3;           // 0..3  (pix 64-block)
    const int P0   = blockIdx.x * 256;
    const int hh0  = P0 >> 6;           // first image row of this tile
    const int cob  = blockIdx.y * 128;
    const int n    = blockIdx.z;

    const int quad = lane >> 3;         // 0..3
    const int lrow = lane & 7;

    // ldmatrix lane-address components (verified fragment mapping from R8)
    const int armBase = wm * 64 + lrow + ((quad & 1) << 3);
    const int akAdd   = (quad >> 1) << 3;
    const int bnBase  = wn * 64 + lrow + ((quad >> 1) << 3);
    const int bkAdd   = (quad & 1) << 3;

    float acc[4][8][4];
#pragma unroll
    for (int mt = 0; mt < 4; mt++)
#pragma unroll
        for (int nt = 0; nt < 8; nt++)
#pragma unroll
            for (int i = 0; i < 4; i++) acc[mt][nt][i] = 0.f;

    for (int ci0 = 0; ci0 < CC; ci0 += 64) {
        __syncthreads();   // all compute on previous chunk's B/A done

        // ---- stage extended B region (hi+lo), zeros at image border --------
        for (int i = tid; i < EXTR * 8; i += 256) {
            int r = i >> 3, q = i & 7;
            int er = r / 66, ec = r - er * 66;
            int ih = hh0 - 1 + er;
            int iw = ec - 1;
            bool valid = ((unsigned)ih < (unsigned)HH) && ((unsigned)iw < (unsigned)WW);
            size_t srow = valid ? (((size_t)n * HW + (ih << 6) + iw) * CC + ci0 + q * 8)
                                : 0;
            int sz = valid ? 16 : 0;
            uint32_t d = (uint32_t)(r * LDB + q * 16);
            cp16(sb32 + OFF_BH + d, g_yth + srow, sz);
            cp16(sb32 + OFF_BL + d, g_ytl + srow, sz);
        }
        // ---- stage A for tap 0 into buffer 0 -------------------------------
        {
            const __nv_bfloat16* srcH = g_wth + ((size_t)cob << 8) + ci0;
            const __nv_bfloat16* srcL = g_wtl + ((size_t)cob << 8) + ci0;
            for (int i = tid; i < 1024; i += 256) {
                int r = i >> 3, q = i & 7;
                uint32_t d = (uint32_t)(r * LDB + q * 16);
                cp16(sb32 + OFF_A + d,        srcH + r * 256 + q * 8, 16);
                cp16(sb32 + OFF_A + A_HL + d, srcL + r * 256 + q * 8, 16);
            }
        }
        CP_COMMIT();

        for (int tap = 0; tap < 9; tap++) {
            __syncthreads();   // protect A buffer (tap+1)&1 from overwrite
            if (tap < 8) {
                const int tn = tap + 1;
                const uint32_t bo = OFF_A + (uint32_t)(tn & 1) * A_BUF;
                const __nv_bfloat16* srcH = g_wth + ((size_t)tn << 16) +
                                            ((size_t)cob << 8) + ci0;
                const __nv_bfloat16* srcL = g_wtl + ((size_t)tn << 16) +
                                            ((size_t)cob << 8) + ci0;
                for (int i = tid; i < 1024; i += 256) {
                    int r = i >> 3, q = i & 7;
                    uint32_t d = bo + (uint32_t)(r * LDB + q * 16);
                    cp16(sb32 + d,        srcH + r * 256 + q * 8, 16);
                    cp16(sb32 + d + A_HL, srcL + r * 256 + q * 8, 16);
                }
                CP_COMMIT();
                CP_WAIT1();          // current tap's A (+B on tap 0) complete
            } else {
                CP_WAIT0();
            }
            __syncthreads();

            // extended-row indices for this tap (per lane, per n-tile pair)
            const int dr = tap / 3 - 1;
            const int ds = tap - (tap / 3) * 3 - 1;
            int eb[4];
#pragma unroll
            for (int ntp = 0; ntp < 4; ntp++) {
                int rl = bnBase + ntp * 16;
                eb[ntp] = ((rl >> 6) + dr + 1) * 66 + (rl & 63) + ds + 1;
            }
            const uint32_t abuf = sb32 + OFF_A + (uint32_t)(tap & 1) * A_BUF;

#pragma unroll
            for (int kk = 0; kk < 4; kk++) {
                const int k0 = kk * 16;
                uint32_t ah[4][4], al[4][4], bh[8][2], bl[8][2];
#pragma unroll
                for (int mt = 0; mt < 4; mt++) {
                    uint32_t aoff = (uint32_t)((armBase + mt * 16) * LDB +
                                               (k0 + akAdd) * 2);
                    ldsm4(ah[mt][0], ah[mt][1], ah[mt][2], ah[mt][3], abuf + aoff);
                    ldsm4(al[mt][0], al[mt][1], al[mt][2], al[mt][3],
                          abuf + A_HL + aoff);
                }
#pragma unroll
                for (int ntp = 0; ntp < 4; ntp++) {
                    uint32_t boff = (uint32_t)(eb[ntp] * LDB + (k0 + bkAdd) * 2);
                    ldsm4(bh[2 * ntp][0], bh[2 * ntp][1],
                          bh[2 * ntp + 1][0], bh[2 * ntp + 1][1],
                          sb32 + OFF_BH + boff);
                    ldsm4(bl[2 * ntp][0], bl[2 * ntp][1],
                          bl[2 * ntp + 1][0], bl[2 * ntp + 1][1],
                          sb32 + OFF_BL + boff);
                }
#pragma unroll
                for (int mt = 0; mt < 4; mt++) {
#pragma unroll
                    for (int nt = 0; nt < 8; nt++) {
                        mma_bf16(acc[mt][nt], ah[mt], bh[nt]);   // hi*hi
                        mma_bf16(acc[mt][nt], ah[mt], bl[nt]);   // hi*lo
                        mma_bf16(acc[mt][nt], al[mt], bh[nt]);   // lo*hi
                    }
                }
            }
        }
    }

    // ---- epilogue: BN + PReLU, store float2 pairs
    const float alpha = a1[0];
#pragma unroll
    for (int mt = 0; mt < 4; mt++) {
        int r0  = wm * 64 + mt * 16 + (lane >> 2);
        int co0 = cob + r0;
        int co1 = co0 + 8;
        float sc0 = g1[co0] * rsqrtf(v1[co0] + BN_EPS);
        float sh0 = b1[co0] - m1[co0] * sc0;
        float sc1 = g1[co1] * rsqrtf(v1[co1] + BN_EPS);
        float sh1 = b1[co1] - m1[co1] * sc1;
        float* base0 = g_h + ((size_t)n * CC + co0) * HW;
        float* base1 = g_h + ((size_t)n * CC + co1) * HW;
#pragma unroll
        for (int nt = 0; nt < 8; nt++) {
            int col = P0 + wn * 64 + nt * 8 + 2 * (lane & 3);
            float v0 = acc[mt][nt][0] * sc0 + sh0;
            float v1_ = acc[mt][nt][1] * sc0 + sh0;
            float v2 = acc[mt][nt][2] * sc1 + sh1;
            float v3 = acc[mt][nt][3] * sc1 + sh1;
            float2 o0, o1;
            o0.x = (v0 >= 0.f) ? v0 : alpha * v0;
            o0.y = (v1_ >= 0.f) ? v1_ : alpha * v1_;
            o1.x = (v2 >= 0.f) ? v2 : alpha * v2;
            o1.y = (v3 >= 0.f) ? v3 : alpha * v3;
            *(float2*)(base0 + col) = o0;
            *(float2*)(base1 + col) = o1;
        }
    }
}

// ===========================================================================
// Kernel 2: 1x1 conv (C->9) + BN + PReLU -> g_kern [N,9,H*W]
// ===========================================================================
__global__ __launch_bounds__(256)
void conv1x1_bn_prelu(const float* __restrict__ W2,
                      const float* __restrict__ g2,
                      const float* __restrict__ b2,
                      const float* __restrict__ m2,
                      const float* __restrict__ v2,
                      const float* __restrict__ a2)
{
    __shared__ float w2s[K2][CC];
    const int tx = threadIdx.x;
    for (int i = tx; i < K2 * CC; i += 256) {
        int k  = i / CC;
        int ci = i - k * CC;
        w2s[k][ci] = W2[k * CC + ci];
    }
    __syncthreads();

    int pix = blockIdx.x * 256 + tx;
    int n   = pix / HW;
    int hw  = pix - n * HW;

    float acc[K2];
#pragma unroll
    for (int k = 0; k < K2; k++) acc[k] = 0.f;

    const float* hp = g_h + (size_t)n * CC * HW + hw;
#pragma unroll 8
    for (int ci = 0; ci < CC; ci++) {
        float v = hp[(size_t)ci * HW];
#pragma unroll
        for (int k = 0; k < K2; k++)
            acc[k] = fmaf(v, w2s[k][ci], acc[k]);
    }

    const float alpha = a2[0];
#pragma unroll
    for (int k = 0; k < K2; k++) {
        float sc = g2[k] * rsqrtf(v2[k] + BN_EPS);
        float sh = b2[k] - m2[k] * sc;
        float v  = acc[k] * sc + sh;
        v = (v >= 0.f) ? v : alpha * v;
        g_kern[((size_t)n * K2 + k) * HW + hw] = v;
    }
}

// ===========================================================================
// Kernel 3: dynamic filter application with torch's ROW-MAJOR reshape scramble
// ===========================================================================
#define G_P 4
#define SLAB 2304
#define SLABP 2305

__global__ __launch_bounds__(256)
void apply_dynamic_kernel(const float* __restrict__ x,
                          float* __restrict__ out)
{
    __shared__ float sA[G_P * SLABP];
    __shared__ float sk[G_P][K2];

    const int tid = threadIdx.x;
    const int P0  = blockIdx.x * G_P;
    const int n   = blockIdx.y;

    if (tid < G_P * K2) {
        int p = tid / K2;
        int k = tid - p * K2;
        sk[p][k] = g_kern[((size_t)n * K2 + k) * HW + P0 + p];
    }

    const float* xn = x + (size_t)n * CC * HW;
    const int base = P0 * SLAB;

    for (int t = tid; t < G_P * SLAB; t += 256) {
        int flat = base + t;
        int w2 = flat & 63;
        int j  = flat >> 6;
        int h2 = j & 63;
        int q  = j >> 6;             // c2*9 + k2
        int k2 = q % 9;
        int c2 = q / 9;
        int r  = k2 / 3;
        int s  = k2 - r * 3;
        int ih = h2 + r - 1;
        int iw = w2 + s - 1;
        float v = 0.f;
        if (ih >= 0 && ih < HH && iw >= 0 && iw < WW)
            v = xn[c2 * HW + ih * WW + iw];
        int slab = t / SLAB;
        int off  = t - slab * SLAB;
        sA[slab * SLABP + off] = v;
    }
    __syncthreads();

    const int c = tid;
    float res[G_P];
#pragma unroll
    for (int p = 0; p < G_P; p++) {
        const float* a = sA + p * SLABP + c * K2;
        float acc = 0.f;
#pragma unroll
        for (int k = 0; k < K2; k++)
            acc = fmaf(a[k], sk[p][k], acc);
        res[p] = acc;
    }

    float* dst = out + ((size_t)n * CC + c) * HW + P0;
#pragma unroll
    for (int p = 0; p < G_P; p++) dst[p] = res[p];
}

// ===========================================================================
extern "C" void kernel_launch(void* const* d_in, const int* in_sizes, int n_in,
                              void* d_out, int out_size)
{
    const float* x  = (const float*)d_in[0];
    const float* y  = (const float*)d_in[1];
    const float* W1 = (const float*)d_in[2];
    const float* g1 = (const float*)d_in[3];
    const float* b1 = (const float*)d_in[4];
    const float* m1 = (const float*)d_in[5];
    const float* v1 = (const float*)d_in[6];
    const float* a1 = (const float*)d_in[7];
    const float* W2 = (const float*)d_in[8];
    const float* g2 = (const float*)d_in[9];
    const float* b2 = (const float*)d_in[10];
    const float* m2 = (const float*)d_in[11];
    const float* v2 = (const float*)d_in[12];
    const float* a2 = (const float*)d_in[13];
    float* out = (float*)d_out;

    static bool attr_set = false;
    if (!attr_set) {
        cudaFuncSetAttribute(conv3x3_mma,
                             cudaFuncAttributeMaxDynamicSharedMemorySize,
                             CONV_SMEM);
        attr_set = true;
    }

    // prep: weight reshape + y transpose to bf16 hi/lo
    prep_weights<<<(K2 * CC * CC + 255) / 256, 256>>>(W1);
    {
        dim3 g(HW / 32, CC / 32, NN);    // (128, 8, 16)
        prep_y_transpose<<<g, 256>>>(y);
    }
    // conv1 on mma.sync tensor cores (pipelined)
    {
        dim3 g(HW / 256, CC / 128, NN);  // (16, 2, 16) = 512 CTAs
        conv3x3_mma<<<g, 256, CONV_SMEM>>>(g1, b1, m1, v1, a1);
    }
    // 1x1 conv
    conv1x1_bn_prelu<<<(NN * HW) / 256, 256>>>(W2, g2, b2, m2, v2, a2);
    // dynamic filter application
    {
        dim3 g(HW / G_P, NN);            // (1024, 16)
        apply_dynamic_kernel<<<g, 256>>>(x, out);
    }
}